// round 4
// baseline (speedup 1.0000x reference)
#include <cuda_runtime.h>

// Fused cosine-score attention, single query — ONE kernel.
//  - Streaming pass over keys (128 MB), 2 rows per warp-iteration (16
//    outstanding LDG.128/warp for MLP), q-slice held in shared memory.
//  - Packed f32x2 FMAs (Blackwell FFMA2 via PTX).
//  - Block smem tree reduction -> 148 block partials in __device__ scratch.
//  - Grid-level tail: ticket counter; last 8 blocks spin until all partials
//    are visible, then each reduces a 128-column slice (fixed summation
//    order -> deterministic). Counters self-reset for graph replay.

#define NBLK 148
#define NTHR 512
#define WPB  (NTHR / 32)           // 16 warps per block
#define NWARPS (NBLK * WPB)        // 2368
#define H 1024
#define ROW_U2 (H / 4)             // 256 ulonglong2 (16B) per row
#define NTAIL 8

typedef unsigned long long u64;

__device__ float4   g_partial[NBLK][H / 4];   // 606 KB scratch
__device__ unsigned g_ticket;                  // zero-init; self-resetting
__device__ unsigned g_finish;

__device__ __forceinline__ u64 ffma2(u64 a, u64 b, u64 c) {
    u64 d;
    asm("fma.rn.f32x2 %0, %1, %2, %3;" : "=l"(d) : "l"(a), "l"(b), "l"(c));
    return d;
}
__device__ __forceinline__ u64 pack2(float x, float y) {
    u64 d;
    asm("mov.b64 %0, {%1, %2};" : "=l"(d) : "f"(x), "f"(y));
    return d;
}
__device__ __forceinline__ float2 unpack2(u64 v) {
    float2 r;
    asm("mov.b64 {%0, %1}, %2;" : "=f"(r.x), "=f"(r.y) : "l"(v));
    return r;
}

__global__ __launch_bounds__(NTHR, 1)
void bahdanau_fused(const float* __restrict__ q,
                    const float* __restrict__ keys, int S,
                    float* __restrict__ out) {
    const int wib  = threadIdx.x >> 5;
    const int warp = blockIdx.x * WPB + wib;
    const int lane = threadIdx.x & 31;

    __shared__ ulonglong2 sq[ROW_U2];          // 4 KB: q row
    __shared__ ulonglong2 red[8][ROW_U2];      // 32 KB: tree reduce / tail

    // Stage q into smem.
    for (int i = threadIdx.x; i < ROW_U2; i += NTHR)
        sq[i] = ((const ulonglong2*)q)[i];
    __syncthreads();

    // |q| (per-warp, cheap, once).
    float qss;
    {
        u64 qs = 0;
#pragma unroll
        for (int i = 0; i < 8; i++) {
            ulonglong2 qv = sq[i * 32 + lane];
            qs = ffma2(qv.x, qv.x, qs);
            qs = ffma2(qv.y, qv.y, qs);
        }
        float2 t = unpack2(qs);
        qss = t.x + t.y;
    }
#pragma unroll
    for (int o = 16; o; o >>= 1) qss += __shfl_xor_sync(0xffffffffu, qss, o);
    const float inv_qn = rsqrtf(qss);

    ulonglong2 acc[8];
#pragma unroll
    for (int i = 0; i < 8; i++) { acc[i].x = 0; acc[i].y = 0; }

    // Main streaming loop: 2 contiguous rows per iteration.
    for (int s = 2 * warp; s < S; s += 2 * NWARPS) {
        const ulonglong2* r0 = (const ulonglong2*)(keys + (size_t)s * H);
        const ulonglong2* r1 = r0 + ROW_U2;

        ulonglong2 k0[8], k1[8];
#pragma unroll
        for (int i = 0; i < 8; i++) k0[i] = r0[i * 32 + lane];
#pragma unroll
        for (int i = 0; i < 8; i++) k1[i] = r1[i * 32 + lane];

        u64 dp0 = 0, kp0 = 0, dp1 = 0, kp1 = 0;
#pragma unroll
        for (int i = 0; i < 8; i++) {
            ulonglong2 qv = sq[i * 32 + lane];
            dp0 = ffma2(k0[i].x, qv.x, dp0);
            dp0 = ffma2(k0[i].y, qv.y, dp0);
            kp0 = ffma2(k0[i].x, k0[i].x, kp0);
            kp0 = ffma2(k0[i].y, k0[i].y, kp0);
            dp1 = ffma2(k1[i].x, qv.x, dp1);
            dp1 = ffma2(k1[i].y, qv.y, dp1);
            kp1 = ffma2(k1[i].x, k1[i].x, kp1);
            kp1 = ffma2(k1[i].y, k1[i].y, kp1);
        }
        float2 a = unpack2(dp0), b = unpack2(kp0);
        float2 c = unpack2(dp1), d = unpack2(kp1);
        float dot0 = a.x + a.y, kss0 = b.x + b.y;
        float dot1 = c.x + c.y, kss1 = d.x + d.y;
#pragma unroll
        for (int o = 16; o; o >>= 1) {
            dot0 += __shfl_xor_sync(0xffffffffu, dot0, o);
            kss0 += __shfl_xor_sync(0xffffffffu, kss0, o);
            dot1 += __shfl_xor_sync(0xffffffffu, dot1, o);
            kss1 += __shfl_xor_sync(0xffffffffu, kss1, o);
        }
        const float sc0 = dot0 * inv_qn * rsqrtf(kss0);
        const float sc1 = dot1 * inv_qn * rsqrtf(kss1);
        const u64 s0 = pack2(sc0, sc0);
        const u64 s1 = pack2(sc1, sc1);
#pragma unroll
        for (int i = 0; i < 8; i++) {
            acc[i].x = ffma2(s0, k0[i].x, acc[i].x);
            acc[i].y = ffma2(s0, k0[i].y, acc[i].y);
            acc[i].x = ffma2(s1, k1[i].x, acc[i].x);
            acc[i].y = ffma2(s1, k1[i].y, acc[i].y);
        }
    }

    // Block tree reduction: 16 -> 8 -> 4 -> 2 -> 1 warps.
#pragma unroll
    for (int half = 8; half >= 1; half >>= 1) {
        if (wib >= half && wib < 2 * half) {
#pragma unroll
            for (int i = 0; i < 8; i++)
                red[wib - half][i * 32 + lane] = acc[i];
        }
        __syncthreads();
        if (wib < half) {
            const u64 one2 = 0x3f8000003f800000ull;
#pragma unroll
            for (int i = 0; i < 8; i++) {
                ulonglong2 v = red[wib][i * 32 + lane];
                acc[i].x = ffma2(v.x, one2, acc[i].x);
                acc[i].y = ffma2(v.y, one2, acc[i].y);
            }
        }
        __syncthreads();
    }

    if (wib == 0) {
#pragma unroll
        for (int i = 0; i < 8; i++)
            *(ulonglong2*)&g_partial[blockIdx.x][i * 32 + lane] = acc[i];
    }

    // Publish partial, take a ticket.
    __threadfence();
    __syncthreads();
    __shared__ unsigned s_t;
    if (threadIdx.x == 0) s_t = atomicAdd(&g_ticket, 1u);
    __syncthreads();
    const unsigned t = s_t;
    if (t < NBLK - NTAIL) return;          // whole block exits together

    // Tail blocks: wait for all partials, then reduce a 128-column slice.
    if (threadIdx.x == 0) {
        while (*(volatile unsigned*)&g_ticket < NBLK) { }
    }
    __syncthreads();
    __threadfence();

    const int slice = (int)t - (NBLK - NTAIL);       // 0..7
    const int col   = slice * 128 + (threadIdx.x & 127);
    const int grp   = threadIdx.x >> 7;              // 0..3
    const float* part = (const float*)g_partial;

    float sum = 0.f;
    for (int p = grp; p < NBLK; p += 4)
        sum += part[(size_t)p * H + col];

    float* shr = (float*)red;
    shr[threadIdx.x] = sum;
    __syncthreads();
    if (threadIdx.x < 128) {
        float tot = shr[threadIdx.x]       + shr[threadIdx.x + 128]
                  + shr[threadIdx.x + 256] + shr[threadIdx.x + 384];
        out[slice * 128 + threadIdx.x] = tot;
    }

    // Reset counters for the next graph replay (last finisher does it).
    __syncthreads();
    if (threadIdx.x == 0) {
        unsigned f = atomicAdd(&g_finish, 1u);
        if (f == NTAIL - 1) { g_ticket = 0; g_finish = 0; }
    }
}

extern "C" void kernel_launch(void* const* d_in, const int* in_sizes, int n_in,
                              void* d_out, int out_size) {
    const float* q    = (const float*)d_in[0];   // [1, 1024]
    const float* keys = (const float*)d_in[1];   // [S, 1024]
    const int S = in_sizes[1] / H;

    bahdanau_fused<<<NBLK, NTHR>>>(q, keys, S, (float*)d_out);
}

// round 6
// speedup vs baseline: 1.0237x; 1.0237x over previous
#include <cuda_runtime.h>

// Fused cosine-score attention, single query — ONE kernel.
//  Main pass = proven R2 body: warp-per-row streaming over keys (128 MB),
//  8 outstanding LDG.128/warp, q + accumulator in registers, block smem
//  tree reduction -> 148 block partials (606 KB) in __device__ scratch.
//  Tail = grid-level ticket sync: last 16 blocks spin until all partials
//  are published, then each reduces a 64-column slice in fixed order
//  (deterministic). Counters self-reset for graph replay.

#define NBLK 148
#define NTHR 512
#define WPB  (NTHR / 32)           // 16 warps per block
#define NWARPS (NBLK * WPB)        // 2368
#define H 1024
#define HV4 (H / 4)                // 256 float4 per row
#define NTAIL 16

__device__ float4   g_partial[NBLK][HV4];   // 606 KB scratch
__device__ unsigned g_ticket;                // zero-init; self-resetting
__device__ unsigned g_finish;

__global__ __launch_bounds__(NTHR, 1)
void bahdanau_fused(const float* __restrict__ q,
                    const float* __restrict__ keys, int S,
                    float* __restrict__ out) {
    const int wib  = threadIdx.x >> 5;
    const int warp = blockIdx.x * WPB + wib;
    const int lane = threadIdx.x & 31;

    __shared__ float4 red[8][HV4];   // 32 KB, reused: tree reduce + tail

    // q slice for this lane + |q|
    const float4* q4 = (const float4*)q;
    float4 qv[8];
    float qss = 0.f;
#pragma unroll
    for (int i = 0; i < 8; i++) {
        qv[i] = q4[i * 32 + lane];
        qss += qv[i].x * qv[i].x + qv[i].y * qv[i].y +
               qv[i].z * qv[i].z + qv[i].w * qv[i].w;
    }
#pragma unroll
    for (int o = 16; o; o >>= 1) qss += __shfl_xor_sync(0xffffffffu, qss, o);
    const float inv_qn = rsqrtf(qss);

    float4 acc[8];
#pragma unroll
    for (int i = 0; i < 8; i++) acc[i] = make_float4(0.f, 0.f, 0.f, 0.f);

    for (int s = warp; s < S; s += NWARPS) {
        const float4* row = (const float4*)(keys + (size_t)s * H);
        float4 kv[8];
        float dot = 0.f, kss = 0.f;
#pragma unroll
        for (int i = 0; i < 8; i++) {
            kv[i] = row[i * 32 + lane];
            dot += kv[i].x * qv[i].x + kv[i].y * qv[i].y +
                   kv[i].z * qv[i].z + kv[i].w * qv[i].w;
            kss += kv[i].x * kv[i].x + kv[i].y * kv[i].y +
                   kv[i].z * kv[i].z + kv[i].w * kv[i].w;
        }
#pragma unroll
        for (int o = 16; o; o >>= 1) {
            dot += __shfl_xor_sync(0xffffffffu, dot, o);
            kss += __shfl_xor_sync(0xffffffffu, kss, o);
        }
        const float score = dot * inv_qn * rsqrtf(kss);
#pragma unroll
        for (int i = 0; i < 8; i++) {
            acc[i].x += score * kv[i].x;
            acc[i].y += score * kv[i].y;
            acc[i].z += score * kv[i].z;
            acc[i].w += score * kv[i].w;
        }
    }

    // Block tree reduction: 16 -> 8 -> 4 -> 2 -> 1 warps.
#pragma unroll
    for (int half = 8; half >= 1; half >>= 1) {
        if (wib >= half && wib < 2 * half) {
#pragma unroll
            for (int i = 0; i < 8; i++)
                red[wib - half][i * 32 + lane] = acc[i];
        }
        __syncthreads();
        if (wib < half) {
#pragma unroll
            for (int i = 0; i < 8; i++) {
                float4 v = red[wib][i * 32 + lane];
                acc[i].x += v.x; acc[i].y += v.y;
                acc[i].z += v.z; acc[i].w += v.w;
            }
        }
        __syncthreads();
    }

    if (wib == 0) {
#pragma unroll
        for (int i = 0; i < 8; i++)
            g_partial[blockIdx.x][i * 32 + lane] = acc[i];
    }

    // Publish partial, take a ticket.
    __threadfence();
    __syncthreads();
    __shared__ unsigned s_t;
    if (threadIdx.x == 0) s_t = atomicAdd(&g_ticket, 1u);
    __syncthreads();
    const unsigned t = s_t;
    if (t < NBLK - NTAIL) return;          // whole block exits together

    // Tail blocks: wait for all partials, then reduce a 64-column slice.
    if (threadIdx.x == 0) {
        while (*(volatile unsigned*)&g_ticket < NBLK) { }
    }
    __syncthreads();
    __threadfence();

    const int slice = (int)t - (NBLK - NTAIL);       // 0..15
    const int col   = slice * 64 + (threadIdx.x & 63);
    const int grp   = threadIdx.x >> 6;              // 0..7
    const float* part = (const float*)g_partial;

    float sum = 0.f;
#pragma unroll
    for (int b = 0; b < 19; b++) {                   // 19*8 = 152 >= 148
        int p = grp + b * 8;
        if (p < NBLK) sum += part[(size_t)p * H + col];
    }

    float* shr = (float*)red;
    shr[threadIdx.x] = sum;
    __syncthreads();
#pragma unroll
    for (int stride = 256; stride >= 64; stride >>= 1) {
        if (threadIdx.x < stride) shr[threadIdx.x] += shr[threadIdx.x + stride];
        __syncthreads();
    }
    if (threadIdx.x < 64) out[slice * 64 + threadIdx.x] = shr[threadIdx.x];

    // Reset counters for the next graph replay (last tail block does it).
    __syncthreads();
    if (threadIdx.x == 0) {
        unsigned f = atomicAdd(&g_finish, 1u);
        if (f == NTAIL - 1) { g_ticket = 0; g_finish = 0; }
    }
}

extern "C" void kernel_launch(void* const* d_in, const int* in_sizes, int n_in,
                              void* d_out, int out_size) {
    const float* q    = (const float*)d_in[0];   // [1, 1024]
    const float* keys = (const float*)d_in[1];   // [S, 1024]
    const int S = in_sizes[1] / H;

    bahdanau_fused<<<NBLK, NTHR>>>(q, keys, S, (float*)d_out);
}

// round 8
// speedup vs baseline: 1.0716x; 1.0468x over previous
#include <cuda_runtime.h>

// Fused cosine-score attention, single query. Two kernels (fused tail was
// measured ~6us SLOWER; split is the proven-fast shape).
// stage1: warp-per-row streaming pass over keys (128 MB) with software L2
//   prefetch 2 iterations ahead (lane L prefetches 128B line L of the future
//   row). Demand LDG.128s then hit L2 (~250cyc) instead of DRAM (~600cyc),
//   shrinking the per-round latency that was capping us at 5.2 TB/s.
//   Block smem tree reduce -> 148 block partials (606 KB).
// stage2: 128-block deterministic reduction of the partials (~4.4us floor).

#define NBLK 148
#define NTHR 512
#define WPB  (NTHR / 32)           // 16 warps per block
#define NWARPS (NBLK * WPB)        // 2368
#define H 1024
#define HV4 (H / 4)                // 256 float4 per row

__device__ float4 g_partial[NBLK][HV4];   // 606 KB scratch

__global__ __launch_bounds__(NTHR, 1)
void bahdanau_stage1(const float* __restrict__ q,
                     const float* __restrict__ keys, int S) {
    const int wib  = threadIdx.x >> 5;
    const int warp = blockIdx.x * WPB + wib;
    const int lane = threadIdx.x & 31;

    __shared__ float4 red[8][HV4];   // 32 KB, reused across reduction phases

    // q slice for this lane + |q|
    const float4* q4 = (const float4*)q;
    float4 qv[8];
    float qss = 0.f;
#pragma unroll
    for (int i = 0; i < 8; i++) {
        qv[i] = q4[i * 32 + lane];
        qss += qv[i].x * qv[i].x + qv[i].y * qv[i].y +
               qv[i].z * qv[i].z + qv[i].w * qv[i].w;
    }
#pragma unroll
    for (int o = 16; o; o >>= 1) qss += __shfl_xor_sync(0xffffffffu, qss, o);
    const float inv_qn = rsqrtf(qss);

    float4 acc[8];
#pragma unroll
    for (int i = 0; i < 8; i++) acc[i] = make_float4(0.f, 0.f, 0.f, 0.f);

    for (int s = warp; s < S; s += NWARPS) {
        // Prefetch the row 2 iterations ahead into L2 (fire-and-forget,
        // no registers held). Lane L covers byte range [L*128, L*128+128).
        const int sp = s + 2 * NWARPS;
        if (sp < S) {
            const char* pf = (const char*)(keys + (size_t)sp * H) + lane * 128;
            asm volatile("prefetch.global.L2 [%0];" :: "l"(pf));
        }

        const float4* row = (const float4*)(keys + (size_t)s * H);
        float4 kv[8];
        float dot = 0.f, kss = 0.f;
#pragma unroll
        for (int i = 0; i < 8; i++) {
            kv[i] = row[i * 32 + lane];
            dot += kv[i].x * qv[i].x + kv[i].y * qv[i].y +
                   kv[i].z * qv[i].z + kv[i].w * qv[i].w;
            kss += kv[i].x * kv[i].x + kv[i].y * kv[i].y +
                   kv[i].z * kv[i].z + kv[i].w * kv[i].w;
        }
#pragma unroll
        for (int o = 16; o; o >>= 1) {
            dot += __shfl_xor_sync(0xffffffffu, dot, o);
            kss += __shfl_xor_sync(0xffffffffu, kss, o);
        }
        const float score = dot * inv_qn * rsqrtf(kss);
#pragma unroll
        for (int i = 0; i < 8; i++) {
            acc[i].x += score * kv[i].x;
            acc[i].y += score * kv[i].y;
            acc[i].z += score * kv[i].z;
            acc[i].w += score * kv[i].w;
        }
    }

    // Block tree reduction: 16 -> 8 -> 4 -> 2 -> 1 warps.
#pragma unroll
    for (int half = 8; half >= 1; half >>= 1) {
        if (wib >= half && wib < 2 * half) {
#pragma unroll
            for (int i = 0; i < 8; i++)
                red[wib - half][i * 32 + lane] = acc[i];
        }
        __syncthreads();
        if (wib < half) {
#pragma unroll
            for (int i = 0; i < 8; i++) {
                float4 v = red[wib][i * 32 + lane];
                acc[i].x += v.x; acc[i].y += v.y;
                acc[i].z += v.z; acc[i].w += v.w;
            }
        }
        __syncthreads();
    }

    if (wib == 0) {
#pragma unroll
        for (int i = 0; i < 8; i++)
            g_partial[blockIdx.x][i * 32 + lane] = acc[i];
    }
}

// stage2: out[h] = sum_{b<148} g_partial[b][h].
// 128 blocks x 256 threads; block owns 8 columns, 32 row-groups per column.
__global__ __launch_bounds__(256)
void bahdanau_stage2(float* __restrict__ out) {
    const int col = blockIdx.x * 8 + (threadIdx.x & 7);
    const int g   = threadIdx.x >> 3;   // 0..31
    const float* part = (const float*)g_partial;

    float s = 0.f;
#pragma unroll
    for (int b = 0; b < 5; b++) {       // 5*32 = 160 >= 148
        int p = g + b * 32;
        if (p < NBLK) s += part[(size_t)p * H + col];
    }

    __shared__ float sh[256];
    sh[threadIdx.x] = s;
    __syncthreads();
#pragma unroll
    for (int stride = 128; stride >= 8; stride >>= 1) {
        if (threadIdx.x < stride) sh[threadIdx.x] += sh[threadIdx.x + stride];
        __syncthreads();
    }
    if (threadIdx.x < 8) out[blockIdx.x * 8 + threadIdx.x] = sh[threadIdx.x];
}

extern "C" void kernel_launch(void* const* d_in, const int* in_sizes, int n_in,
                              void* d_out, int out_size) {
    const float* q    = (const float*)d_in[0];   // [1, 1024]
    const float* keys = (const float*)d_in[1];   // [S, 1024]
    const int S = in_sizes[1] / H;

    bahdanau_stage1<<<NBLK, NTHR>>>(q, keys, S);
    bahdanau_stage2<<<H / 8, 256>>>((float*)d_out);
}

// round 9
// speedup vs baseline: 1.2196x; 1.1380x over previous
#include <cuda_runtime.h>

// Fused cosine-score attention, single query. Two kernels (fused tail was
// measured slower; split is the proven shape).
//
// stage1: cp.async (LDGSTS) double-buffered smem pipeline. Global->shared
//   copies hold the DRAM traffic in flight WITHOUT registers (the previous
//   5.2 TB/s cap was the register-file bound on outstanding LDG data).
//   2 stages x 16 rows x 4KB = 128 KB smem; each warp computes one row per
//   tile from smem (dot, |k|, score, score*k accumulate), block tree-reduce
//   -> 148 partials (606 KB scratch).
// stage2: 128-block deterministic reduction of the partials.

#define NBLK 148
#define NTHR 512
#define WPB  (NTHR / 32)            // 16 warps
#define H 1024
#define HV4 (H / 4)
#define TROWS 16                    // rows per tile (one per warp)
#define TFLOATS (TROWS * H)         // 16384 floats = 64 KB
#define NSTAGE 2
#define SMEM_BYTES (NSTAGE * TFLOATS * 4)   // 128 KB

__device__ float4 g_partial[NBLK][HV4];     // 606 KB scratch

__device__ __forceinline__ unsigned smem_u32(const void* p) {
    unsigned a;
    asm("{ .reg .u64 t; cvta.to.shared.u64 t, %1; cvt.u32.u64 %0, t; }"
        : "=r"(a) : "l"(p));
    return a;
}
__device__ __forceinline__ void cp16(unsigned dst, const void* src) {
    asm volatile("cp.async.cg.shared.global [%0], [%1], 16;"
                 :: "r"(dst), "l"(src));
}
__device__ __forceinline__ void cp_commit() {
    asm volatile("cp.async.commit_group;");
}
__device__ __forceinline__ void cp_wait1() {
    asm volatile("cp.async.wait_group 1;");
}
__device__ __forceinline__ void cp_wait0() {
    asm volatile("cp.async.wait_group 0;");
}

__global__ __launch_bounds__(NTHR, 1)
void bahdanau_stage1(const float* __restrict__ q,
                     const float* __restrict__ keys, int S) {
    extern __shared__ float smem[];            // NSTAGE * TFLOATS
    const int wib  = threadIdx.x >> 5;
    const int lane = threadIdx.x & 31;
    const unsigned smem_base = smem_u32(smem);

    // q slice in registers + |q|
    const float4* q4 = (const float4*)q;
    float4 qv[8];
    float qss = 0.f;
#pragma unroll
    for (int i = 0; i < 8; i++) {
        qv[i] = q4[i * 32 + lane];
        qss += qv[i].x * qv[i].x + qv[i].y * qv[i].y +
               qv[i].z * qv[i].z + qv[i].w * qv[i].w;
    }
#pragma unroll
    for (int o = 16; o; o >>= 1) qss += __shfl_xor_sync(0xffffffffu, qss, o);
    const float inv_qn = rsqrtf(qss);

    float4 acc[8];
#pragma unroll
    for (int i = 0; i < 8; i++) acc[i] = make_float4(0.f, 0.f, 0.f, 0.f);

    const int nchunk = (S + TROWS - 1) / TROWS;

    // Issue one tile copy (64 KB, 8 x 16B per thread). Always commits a
    // group (possibly empty) so wait_group counting stays aligned.
    auto issue = [&](int c, int stg) {
        if (c < nchunk) {
            const char* src = (const char*)(keys + (size_t)c * TROWS * H);
            const unsigned dst = smem_base + stg * (TFLOATS * 4);
            int nbytes = S - c * TROWS;
            nbytes = (nbytes > TROWS ? TROWS : nbytes) * H * 4;
            for (int off = threadIdx.x * 16; off < nbytes; off += NTHR * 16)
                cp16(dst + off, src + off);
        }
        cp_commit();
    };

    int c = blockIdx.x;
    issue(c, 0);
    issue(c + NBLK, 1);

    int stg = 0;
    for (; c < nchunk; c += NBLK, stg ^= 1) {
        cp_wait1();
        __syncthreads();

        const int row = c * TROWS + wib;
        if (row < S) {
            const float4* srow =
                (const float4*)(smem + stg * TFLOATS + wib * H);
            float4 kv[8];
            float dot = 0.f, kss = 0.f;
#pragma unroll
            for (int i = 0; i < 8; i++) {
                kv[i] = srow[i * 32 + lane];
                dot += kv[i].x * qv[i].x + kv[i].y * qv[i].y +
                       kv[i].z * qv[i].z + kv[i].w * qv[i].w;
                kss += kv[i].x * kv[i].x + kv[i].y * kv[i].y +
                       kv[i].z * kv[i].z + kv[i].w * kv[i].w;
            }
#pragma unroll
            for (int o = 16; o; o >>= 1) {
                dot += __shfl_xor_sync(0xffffffffu, dot, o);
                kss += __shfl_xor_sync(0xffffffffu, kss, o);
            }
            const float score = dot * inv_qn * rsqrtf(kss);
#pragma unroll
            for (int i = 0; i < 8; i++) {
                acc[i].x += score * kv[i].x;
                acc[i].y += score * kv[i].y;
                acc[i].z += score * kv[i].z;
                acc[i].w += score * kv[i].w;
            }
        }
        __syncthreads();
        issue(c + 2 * NBLK, stg);
    }

    cp_wait0();
    __syncthreads();

    // Block tree reduction (scratch aliases the tile buffer): 16 -> ... -> 1.
    float4 (*red)[HV4] = (float4 (*)[HV4])smem;   // 32 KB of the 128 KB
#pragma unroll
    for (int half = 8; half >= 1; half >>= 1) {
        if (wib >= half && wib < 2 * half) {
#pragma unroll
            for (int i = 0; i < 8; i++)
                red[wib - half][i * 32 + lane] = acc[i];
        }
        __syncthreads();
        if (wib < half) {
#pragma unroll
            for (int i = 0; i < 8; i++) {
                float4 v = red[wib][i * 32 + lane];
                acc[i].x += v.x; acc[i].y += v.y;
                acc[i].z += v.z; acc[i].w += v.w;
            }
        }
        __syncthreads();
    }

    if (wib == 0) {
#pragma unroll
        for (int i = 0; i < 8; i++)
            g_partial[blockIdx.x][i * 32 + lane] = acc[i];
    }
}

// stage2: out[h] = sum_{b<148} g_partial[b][h].
__global__ __launch_bounds__(256)
void bahdanau_stage2(float* __restrict__ out) {
    const int col = blockIdx.x * 8 + (threadIdx.x & 7);
    const int g   = threadIdx.x >> 3;   // 0..31
    const float* part = (const float*)g_partial;

    float s = 0.f;
#pragma unroll
    for (int b = 0; b < 5; b++) {       // 5*32 = 160 >= 148
        int p = g + b * 32;
        if (p < NBLK) s += part[(size_t)p * H + col];
    }

    __shared__ float sh[256];
    sh[threadIdx.x] = s;
    __syncthreads();
#pragma unroll
    for (int stride = 128; stride >= 8; stride >>= 1) {
        if (threadIdx.x < stride) sh[threadIdx.x] += sh[threadIdx.x + stride];
        __syncthreads();
    }
    if (threadIdx.x < 8) out[blockIdx.x * 8 + threadIdx.x] = sh[threadIdx.x];
}

extern "C" void kernel_launch(void* const* d_in, const int* in_sizes, int n_in,
                              void* d_out, int out_size) {
    const float* q    = (const float*)d_in[0];   // [1, 1024]
    const float* keys = (const float*)d_in[1];   // [S, 1024]
    const int S = in_sizes[1] / H;

    cudaFuncSetAttribute(bahdanau_stage1,
                         cudaFuncAttributeMaxDynamicSharedMemorySize,
                         SMEM_BYTES);
    bahdanau_stage1<<<NBLK, NTHR, SMEM_BYTES>>>(q, keys, S);
    bahdanau_stage2<<<H / 8, 256>>>((float*)d_out);
}